// round 7
// baseline (speedup 1.0000x reference)
#include <cuda_runtime.h>
#include <cuda_bf16.h>
#include <math.h>

#define KK   64
#define DD   320
#define NN   2048
#define MM   128
#define SS   (KK * MM)        // 8192
#define DB   4                // dims per gather block (contiguous chunk)
#define NB   (DD / DB)        // 80
#define EPSN 1e-12f
#define FBLK 128              // fused blocks, 1 per SM, all co-resident
#define FTPB 512              // 16 warps
#define RPW  4                // rows per warp: 128*16*4 = 8192

// ---------------- device scratch (plain stores only; nothing needs init) ----
__device__ int   g_perm[KK * NN];        // packed (cid<<16)|n, sorted per cloud
__device__ float g_counts[SS];
__device__ int   g_cls[SS];
__device__ float g_blkmax[KK];
__device__ float g_vpart[FBLK * DD];
__device__ float g_msum_p[FBLK];
__device__ float g_mcnt_p[FBLK];
__device__ int   g_sync1;                // monotonic round counters
__device__ int   g_sync2;

// ---------------- A: counts / class mask / packed sorted perm / blockmax ----
__global__ __launch_bounds__(256)
void k_counts(const float* __restrict__ label,
              const int*   __restrict__ clab) {
    __shared__ float s_cnt[MM];
    __shared__ float s_lbl[MM];
    __shared__ int   s_off[MM];
    __shared__ int   s_cur[MM];
    __shared__ float s_size[MM];
    int k = blockIdx.x;
    int tid = threadIdx.x;
    int lane = tid & 31;
    if (tid < MM) { s_cnt[tid] = 0.0f; s_lbl[tid] = 0.0f; }
    __syncthreads();
    const int base = k * NN;
    const int4*   cg = (const int4*)(clab + base);
    const float4* lg = (const float4*)(label + base);
    int4 c4[2]; float4 l4[2];
    #pragma unroll
    for (int i = 0; i < 2; ++i) {
        c4[i] = cg[tid + 256 * i];
        l4[i] = lg[tid + 256 * i];
        atomicAdd(&s_cnt[c4[i].x], 1.0f); atomicAdd(&s_lbl[c4[i].x], l4[i].x);
        atomicAdd(&s_cnt[c4[i].y], 1.0f); atomicAdd(&s_lbl[c4[i].y], l4[i].y);
        atomicAdd(&s_cnt[c4[i].z], 1.0f); atomicAdd(&s_lbl[c4[i].z], l4[i].z);
        atomicAdd(&s_cnt[c4[i].w], 1.0f); atomicAdd(&s_lbl[c4[i].w], l4[i].w);
    }
    __syncthreads();
    if (tid < 32) {   // warp exclusive scan of 128 counts
        int e0 = (int)s_cnt[lane * 4 + 0];
        int e1 = (int)s_cnt[lane * 4 + 1];
        int e2 = (int)s_cnt[lane * 4 + 2];
        int e3 = (int)s_cnt[lane * 4 + 3];
        int t  = e0 + e1 + e2 + e3;
        int pre = t;
        #pragma unroll
        for (int o = 1; o < 32; o <<= 1) {
            int nb = __shfl_up_sync(0xffffffffu, pre, o);
            if (lane >= o) pre += nb;
        }
        int ex = pre - t;
        s_off[lane * 4 + 0] = ex;
        s_off[lane * 4 + 1] = ex + e0;
        s_off[lane * 4 + 2] = ex + e0 + e1;
        s_off[lane * 4 + 3] = ex + e0 + e1 + e2;
    }
    __syncthreads();
    if (tid < MM) {
        int s = k * MM + tid;
        float c  = s_cnt[tid];
        float dn = fmaxf(c, 1.0f);
        float lm = s_lbl[tid] / dn;
        int cls  = (lm > 0.5f) && (c > 0.0f);
        g_counts[s] = c;
        g_cls[s]    = cls;
        s_cur[tid]  = s_off[tid];
        s_size[tid] = cls ? c : 0.0f;
    }
    __syncthreads();
    if (tid < 32) {   // per-cloud max size (plain store, no global atomics)
        float m = fmaxf(fmaxf(s_size[lane], s_size[lane + 32]),
                        fmaxf(s_size[lane + 64], s_size[lane + 96]));
        #pragma unroll
        for (int o = 16; o > 0; o >>= 1)
            m = fmaxf(m, __shfl_xor_sync(0xffffffffu, m, o));
        if (lane == 0) g_blkmax[k] = m;
    }
    #pragma unroll
    for (int i = 0; i < 2; ++i) {
        int n0 = (tid + 256 * i) * 4;
        int p;
        p = atomicAdd(&s_cur[c4[i].x], 1); g_perm[base + p] = (c4[i].x << 16) | (n0 + 0);
        p = atomicAdd(&s_cur[c4[i].y], 1); g_perm[base + p] = (c4[i].y << 16) | (n0 + 1);
        p = atomicAdd(&s_cur[c4[i].z], 1); g_perm[base + p] = (c4[i].z << 16) | (n0 + 2);
        p = atomicAdd(&s_cur[c4[i].w], 1); g_perm[base + p] = (c4[i].w << 16) | (n0 + 3);
    }
}

// ---------------- B: balanced segmented gather -> cluster_means ----------------
// 512 thr; thread t: stages pts 4t..4t+3 (transposed float4), then accumulates
// sorted positions 4t..4t+3 with boundary flushes. Perfect load balance.
__global__ __launch_bounds__(512)
void k_gather(const float* __restrict__ feat,
              float*       __restrict__ out_cm) {
    __shared__ __align__(16) float4 s_ft[NN];     // 32 KB: [pt] -> 4 dims
    __shared__ float s_acc[MM * DB];              // 2 KB
    int k     = blockIdx.x / NB;
    int dbase = (blockIdx.x % NB) * DB;
    int tid   = threadIdx.x;

    s_acc[tid] = 0.0f;   // MM*DB == 512

    int4 pc = ((const int4*)(g_perm + k * NN))[tid];

    // transposed staging: 4 coalesced LDG.128 -> register transpose -> 4 STS.128
    const float* fb = feat + ((size_t)k * DD + dbase) * NN;
    float4 r0 = ((const float4*)(fb + 0 * NN))[tid];
    float4 r1 = ((const float4*)(fb + 1 * NN))[tid];
    float4 r2 = ((const float4*)(fb + 2 * NN))[tid];
    float4 r3 = ((const float4*)(fb + 3 * NN))[tid];
    s_ft[4 * tid + 0] = make_float4(r0.x, r1.x, r2.x, r3.x);
    s_ft[4 * tid + 1] = make_float4(r0.y, r1.y, r2.y, r3.y);
    s_ft[4 * tid + 2] = make_float4(r0.z, r1.z, r2.z, r3.z);
    s_ft[4 * tid + 3] = make_float4(r0.w, r1.w, r2.w, r3.w);
    __syncthreads();

    int pk[4] = {pc.x, pc.y, pc.z, pc.w};
    int prev = pk[0] >> 16;
    float4 f = s_ft[pk[0] & 0xFFFF];
    float4 acc = f;
    #pragma unroll
    for (int j = 1; j < 4; ++j) {
        int cid = pk[j] >> 16;
        if (cid != prev) {
            atomicAdd(&s_acc[prev * 4 + 0], acc.x);
            atomicAdd(&s_acc[prev * 4 + 1], acc.y);
            atomicAdd(&s_acc[prev * 4 + 2], acc.z);
            atomicAdd(&s_acc[prev * 4 + 3], acc.w);
            acc = make_float4(0.f, 0.f, 0.f, 0.f);
            prev = cid;
        }
        f = s_ft[pk[j] & 0xFFFF];
        acc.x += f.x; acc.y += f.y; acc.z += f.z; acc.w += f.w;
    }
    atomicAdd(&s_acc[prev * 4 + 0], acc.x);
    atomicAdd(&s_acc[prev * 4 + 1], acc.y);
    atomicAdd(&s_acc[prev * 4 + 2], acc.z);
    atomicAdd(&s_acc[prev * 4 + 3], acc.w);
    __syncthreads();

    if (tid < MM) {
        int s = k * MM + tid;
        float dn = fmaxf(g_counts[s], 1.0f);
        float4 o = make_float4(s_acc[tid * 4 + 0] / dn, s_acc[tid * 4 + 1] / dn,
                               s_acc[tid * 4 + 2] / dn, s_acc[tid * 4 + 3] / dn);
        *(float4*)(out_cm + (size_t)s * DD + dbase) = o;
    }
}

// ---------------- F: fused norms + v + sim + mean + clean ----------------
// 128 blocks x 512 thr (1 block/SM). No global atomics for data; grid syncs
// use monotonic round counters (graph-replay safe, no re-init needed).
__global__ void __launch_bounds__(FTPB, 1)
k_fused(const float* __restrict__ cm,
        float* __restrict__ out_sim,
        float* __restrict__ out_clean) {
    __shared__ __align__(16) float s_v[DD];
    __shared__ float s_ms[16];
    __shared__ float s_mc[16];
    __shared__ float s_md;
    __shared__ float s_mean;
    int tid  = threadIdx.x;
    int warp = tid >> 5;
    int lane = tid & 31;
    const float4 z4 = make_float4(0.f, 0.f, 0.f, 0.f);

    if (tid < DD) s_v[tid] = 0.0f;
    if (warp == 0) {   // maxden from per-cloud maxes
        float m = fmaxf(g_blkmax[lane], g_blkmax[lane + 32]);
        #pragma unroll
        for (int o = 16; o > 0; o >>= 1)
            m = fmaxf(m, __shfl_xor_sync(0xffffffffu, m, o));
        if (lane == 0) s_md = fmaxf(m, 1.0f);
    }

    const int base = blockIdx.x * (16 * RPW) + warp * RPW;

    // batch ALL row loads first (max MLP)
    float4 x0[RPW], x1[RPW], x2[RPW];
    #pragma unroll
    for (int i = 0; i < RPW; ++i) {
        const float4* rp = (const float4*)(cm + (size_t)(base + i) * DD);
        x0[i] = rp[lane];
        x1[i] = rp[32 + lane];
        x2[i] = (lane < 16) ? rp[64 + lane] : z4;
    }
    __syncthreads();
    float maxden = s_md;

    float bfac[RPW];
    int   cls[RPW];
    float4 a0 = z4, a1 = z4, a2 = z4;
    #pragma unroll
    for (int i = 0; i < RPW; ++i) {
        int s = base + i;
        float ss = x0[i].x * x0[i].x + x0[i].y * x0[i].y + x0[i].z * x0[i].z + x0[i].w * x0[i].w
                 + x1[i].x * x1[i].x + x1[i].y * x1[i].y + x1[i].z * x1[i].z + x1[i].w * x1[i].w
                 + x2[i].x * x2[i].x + x2[i].y * x2[i].y + x2[i].z * x2[i].z + x2[i].w * x2[i].w;
        #pragma unroll
        for (int o = 16; o > 0; o >>= 1) ss += __shfl_xor_sync(0xffffffffu, ss, o);
        float invn = 1.0f / fmaxf(sqrtf(ss), EPSN);
        cls[i]  = g_cls[s];
        bfac[i] = cls[i] ? invn : 0.0f;
        float a = cls[i] ? invn * (g_counts[s] / maxden) : 0.0f;
        a0.x += x0[i].x * a; a0.y += x0[i].y * a; a0.z += x0[i].z * a; a0.w += x0[i].w * a;
        a1.x += x1[i].x * a; a1.y += x1[i].y * a; a1.z += x1[i].z * a; a1.w += x1[i].w * a;
        a2.x += x2[i].x * a; a2.y += x2[i].y * a; a2.z += x2[i].z * a; a2.w += x2[i].w * a;
    }
    // block v-partial: smem atomics (16 warps, distinct addrs per lane)
    atomicAdd(&s_v[4 * lane + 0], a0.x); atomicAdd(&s_v[4 * lane + 1], a0.y);
    atomicAdd(&s_v[4 * lane + 2], a0.z); atomicAdd(&s_v[4 * lane + 3], a0.w);
    atomicAdd(&s_v[128 + 4 * lane + 0], a1.x); atomicAdd(&s_v[128 + 4 * lane + 1], a1.y);
    atomicAdd(&s_v[128 + 4 * lane + 2], a1.z); atomicAdd(&s_v[128 + 4 * lane + 3], a1.w);
    if (lane < 16) {
        atomicAdd(&s_v[256 + 4 * lane + 0], a2.x); atomicAdd(&s_v[256 + 4 * lane + 1], a2.y);
        atomicAdd(&s_v[256 + 4 * lane + 2], a2.z); atomicAdd(&s_v[256 + 4 * lane + 3], a2.w);
    }
    __syncthreads();
    if (tid < DD) g_vpart[blockIdx.x * DD + tid] = s_v[tid];   // plain coalesced STG
    __threadfence();
    __syncthreads();

    // ---- grid sync #1 (monotonic round counter) ----
    if (tid == 0) {
        int arr = atomicAdd(&g_sync1, 1);
        int tgt = (arr / FBLK + 1) * FBLK;
        while (*(volatile int*)&g_sync1 < tgt) __nanosleep(64);
        __threadfence();
    }
    __syncthreads();

    // column-sum the 128 partials (coalesced; ~160KB L2 per block)
    if (tid < DD) {
        float v = 0.0f;
        #pragma unroll 4
        for (int b = 0; b < FBLK; ++b) v += __ldcg(&g_vpart[b * DD + tid]);
        s_v[tid] = v;
    }
    __syncthreads();

    const float4* v4 = (const float4*)s_v;
    float4 v0 = v4[lane];
    float4 v1 = v4[32 + lane];
    float4 v2 = (lane < 16) ? v4[64 + lane] : z4;

    float sim[RPW];
    float psum = 0.0f, pcnt = 0.0f;
    #pragma unroll
    for (int i = 0; i < RPW; ++i) {
        float dot = x0[i].x * v0.x + x0[i].y * v0.y + x0[i].z * v0.z + x0[i].w * v0.w
                  + x1[i].x * v1.x + x1[i].y * v1.y + x1[i].z * v1.z + x1[i].w * v1.w
                  + x2[i].x * v2.x + x2[i].y * v2.y + x2[i].z * v2.z + x2[i].w * v2.w;
        #pragma unroll
        for (int o = 16; o > 0; o >>= 1) dot += __shfl_xor_sync(0xffffffffu, dot, o);
        sim[i] = bfac[i] * dot;
        if (lane == 0) {
            out_sim[base + i] = sim[i];
            if (cls[i]) { psum += sim[i]; pcnt += 1.0f; }
        }
    }
    if (lane == 0) { s_ms[warp] = psum; s_mc[warp] = pcnt; }
    __syncthreads();
    if (tid == 0) {
        float bs = 0.0f, bc = 0.0f;
        #pragma unroll
        for (int w = 0; w < 16; ++w) { bs += s_ms[w]; bc += s_mc[w]; }
        g_msum_p[blockIdx.x] = bs;   // plain stores
        g_mcnt_p[blockIdx.x] = bc;
    }
    __threadfence();
    __syncthreads();

    // ---- grid sync #2 ----
    if (tid == 0) {
        int arr = atomicAdd(&g_sync2, 1);
        int tgt = (arr / FBLK + 1) * FBLK;
        while (*(volatile int*)&g_sync2 < tgt) __nanosleep(64);
        __threadfence();
    }
    __syncthreads();

    if (warp == 0) {   // redundant tiny mean reduce per block
        float bs = 0.0f, bc = 0.0f;
        #pragma unroll
        for (int j = 0; j < 4; ++j) {
            bs += *(volatile float*)&g_msum_p[lane + 32 * j];
            bc += *(volatile float*)&g_mcnt_p[lane + 32 * j];
        }
        #pragma unroll
        for (int o = 16; o > 0; o >>= 1) {
            bs += __shfl_xor_sync(0xffffffffu, bs, o);
            bc += __shfl_xor_sync(0xffffffffu, bc, o);
        }
        if (lane == 0) s_mean = bs / fmaxf(bc, 1.0f);
    }
    __syncthreads();
    float mean = s_mean;
    if (lane == 0) {
        #pragma unroll
        for (int i = 0; i < RPW; ++i)
            out_clean[base + i] = ((sim[i] > mean) && cls[i]) ? 1.0f : 0.0f;
    }
}

// ---------------- launch ----------------
extern "C" void kernel_launch(void* const* d_in, const int* in_sizes, int n_in,
                              void* d_out, int out_size) {
    const float* feat  = (const float*)d_in[0];
    const float* label = (const float*)d_in[1];
    const int*   clab  = (const int*)d_in[2];
    float* out = (float*)d_out;
    float* out_cm    = out;
    float* out_sim   = out + (size_t)SS * DD;
    float* out_clean = out + (size_t)SS * DD + SS;

    k_counts<<<KK, 256>>>(label, clab);
    k_gather<<<KK * NB, 512>>>(feat, out_cm);
    k_fused<<<FBLK, FTPB>>>(out_cm, out_sim, out_clean);
}

// round 8
// speedup vs baseline: 1.1505x; 1.1505x over previous
#include <cuda_runtime.h>
#include <cuda_bf16.h>
#include <math.h>

#define KK   64
#define DD   320
#define NN   2048
#define MM   128
#define SS   (KK * MM)        // 8192
#define DB   4                // dims per gather block (contiguous chunk)
#define NB   (DD / DB)        // 80
#define EPSN 1e-12f
#define FBLK 128              // fused blocks, 1 per SM, all co-resident
#define FTPB 512              // 16 warps
#define RPW  4                // rows per warp: 128*16*4 = 8192

// swizzled transposed-feat index: perfect STS.128 bankgroup permutation
#define SWIZ(p) (((p) & ~3) | (((p) + ((p) >> 3)) & 3))

// ---------------- device scratch (plain stores only; nothing needs init) ----
__device__ int   g_perm[KK * NN];        // packed (cid<<16)|n, sorted per cloud
__device__ float g_counts[SS];
__device__ int   g_cls[SS];
__device__ float g_blkmax[KK];
__device__ float g_vpart[FBLK * DD];
__device__ float g_msum_p[FBLK];
__device__ float g_mcnt_p[FBLK];
__device__ int   g_sync1;                // monotonic round counters
__device__ int   g_sync2;

// ---------------- A: counts / class mask / packed sorted perm / blockmax ----
__global__ __launch_bounds__(512)
void k_counts(const float* __restrict__ label,
              const int*   __restrict__ clab) {
    __shared__ float s_cnt[MM];
    __shared__ float s_lbl[MM];
    __shared__ int   s_off[MM];
    __shared__ int   s_cur[MM];
    __shared__ float s_size[MM];
    int k = blockIdx.x;
    int tid = threadIdx.x;
    int lane = tid & 31;
    if (tid < MM) { s_cnt[tid] = 0.0f; s_lbl[tid] = 0.0f; }
    __syncthreads();
    const int base = k * NN;
    int4   c4 = ((const int4*)(clab + base))[tid];
    float4 l4 = ((const float4*)(label + base))[tid];
    atomicAdd(&s_cnt[c4.x], 1.0f); atomicAdd(&s_lbl[c4.x], l4.x);
    atomicAdd(&s_cnt[c4.y], 1.0f); atomicAdd(&s_lbl[c4.y], l4.y);
    atomicAdd(&s_cnt[c4.z], 1.0f); atomicAdd(&s_lbl[c4.z], l4.z);
    atomicAdd(&s_cnt[c4.w], 1.0f); atomicAdd(&s_lbl[c4.w], l4.w);
    __syncthreads();
    if (tid < 32) {   // warp exclusive scan of 128 counts
        int e0 = (int)s_cnt[lane * 4 + 0];
        int e1 = (int)s_cnt[lane * 4 + 1];
        int e2 = (int)s_cnt[lane * 4 + 2];
        int e3 = (int)s_cnt[lane * 4 + 3];
        int t  = e0 + e1 + e2 + e3;
        int pre = t;
        #pragma unroll
        for (int o = 1; o < 32; o <<= 1) {
            int nb = __shfl_up_sync(0xffffffffu, pre, o);
            if (lane >= o) pre += nb;
        }
        int ex = pre - t;
        s_off[lane * 4 + 0] = ex;
        s_off[lane * 4 + 1] = ex + e0;
        s_off[lane * 4 + 2] = ex + e0 + e1;
        s_off[lane * 4 + 3] = ex + e0 + e1 + e2;
    }
    __syncthreads();
    if (tid < MM) {
        int s = k * MM + tid;
        float c  = s_cnt[tid];
        float dn = fmaxf(c, 1.0f);
        float lm = s_lbl[tid] / dn;
        int cls  = (lm > 0.5f) && (c > 0.0f);
        g_counts[s] = c;
        g_cls[s]    = cls;
        s_cur[tid]  = s_off[tid];
        s_size[tid] = cls ? c : 0.0f;
    }
    __syncthreads();
    if (tid < 32) {   // per-cloud max size (plain store, no global atomics)
        float m = fmaxf(fmaxf(s_size[lane], s_size[lane + 32]),
                        fmaxf(s_size[lane + 64], s_size[lane + 96]));
        #pragma unroll
        for (int o = 16; o > 0; o >>= 1)
            m = fmaxf(m, __shfl_xor_sync(0xffffffffu, m, o));
        if (lane == 0) g_blkmax[k] = m;
    }
    {
        int n0 = tid * 4;
        int p;
        p = atomicAdd(&s_cur[c4.x], 1); g_perm[base + p] = (c4.x << 16) | (n0 + 0);
        p = atomicAdd(&s_cur[c4.y], 1); g_perm[base + p] = (c4.y << 16) | (n0 + 1);
        p = atomicAdd(&s_cur[c4.z], 1); g_perm[base + p] = (c4.z << 16) | (n0 + 2);
        p = atomicAdd(&s_cur[c4.w], 1); g_perm[base + p] = (c4.w << 16) | (n0 + 3);
    }
}

// ---------------- B: balanced segmented gather -> cluster_means ----------------
// 512 thr; thread t stages pts 4t..4t+3 transposed at SWIZZLED indices
// (conflict-free STS.128), then accumulates sorted positions 4t..4t+3 via
// LDS.128 with boundary flushes. Perfect load balance, no global atomics.
__global__ __launch_bounds__(512)
void k_gather(const float* __restrict__ feat,
              float*       __restrict__ out_cm) {
    __shared__ __align__(16) float4 s_ft[NN];     // 32 KB: [SWIZ(pt)] -> 4 dims
    __shared__ float s_acc[MM * DB];              // 2 KB
    int k     = blockIdx.x / NB;
    int dbase = (blockIdx.x % NB) * DB;
    int tid   = threadIdx.x;

    s_acc[tid] = 0.0f;   // MM*DB == 512

    int4 pc = ((const int4*)(g_perm + k * NN))[tid];

    // coalesced streaming loads of 4 dim-rows, register transpose,
    // swizzled STS.128 (bankgroup-perfect)
    const float* fb = feat + ((size_t)k * DD + dbase) * NN;
    float4 r0 = __ldcs((const float4*)(fb + 0 * NN) + tid);
    float4 r1 = __ldcs((const float4*)(fb + 1 * NN) + tid);
    float4 r2 = __ldcs((const float4*)(fb + 2 * NN) + tid);
    float4 r3 = __ldcs((const float4*)(fb + 3 * NN) + tid);
    int b  = 4 * tid;
    int sw = (tid >> 1) & 3;
    s_ft[b + ((0 + sw) & 3)] = make_float4(r0.x, r1.x, r2.x, r3.x);
    s_ft[b + ((1 + sw) & 3)] = make_float4(r0.y, r1.y, r2.y, r3.y);
    s_ft[b + ((2 + sw) & 3)] = make_float4(r0.z, r1.z, r2.z, r3.z);
    s_ft[b + ((3 + sw) & 3)] = make_float4(r0.w, r1.w, r2.w, r3.w);
    __syncthreads();

    int pk[4] = {pc.x, pc.y, pc.z, pc.w};
    int prev = pk[0] >> 16;
    float4 acc = s_ft[SWIZ(pk[0] & 0xFFFF)];
    #pragma unroll
    for (int j = 1; j < 4; ++j) {
        int cid = pk[j] >> 16;
        float4 f = s_ft[SWIZ(pk[j] & 0xFFFF)];
        if (cid != prev) {
            atomicAdd(&s_acc[prev * 4 + 0], acc.x);
            atomicAdd(&s_acc[prev * 4 + 1], acc.y);
            atomicAdd(&s_acc[prev * 4 + 2], acc.z);
            atomicAdd(&s_acc[prev * 4 + 3], acc.w);
            acc = f;
            prev = cid;
        } else {
            acc.x += f.x; acc.y += f.y; acc.z += f.z; acc.w += f.w;
        }
    }
    atomicAdd(&s_acc[prev * 4 + 0], acc.x);
    atomicAdd(&s_acc[prev * 4 + 1], acc.y);
    atomicAdd(&s_acc[prev * 4 + 2], acc.z);
    atomicAdd(&s_acc[prev * 4 + 3], acc.w);
    __syncthreads();

    if (tid < MM) {
        int s = k * MM + tid;
        float dn = fmaxf(g_counts[s], 1.0f);
        float4 o = make_float4(s_acc[tid * 4 + 0] / dn, s_acc[tid * 4 + 1] / dn,
                               s_acc[tid * 4 + 2] / dn, s_acc[tid * 4 + 3] / dn);
        *(float4*)(out_cm + (size_t)s * DD + dbase) = o;
    }
}

// ---------------- F: fused norms + v + sim + mean + clean ----------------
// 128 blocks x 512 thr (1 block/SM). No global atomics for data; grid syncs
// use monotonic round counters (graph-replay safe, no re-init needed).
__global__ void __launch_bounds__(FTPB, 1)
k_fused(const float* __restrict__ cm,
        float* __restrict__ out_sim,
        float* __restrict__ out_clean) {
    __shared__ __align__(16) float s_v[DD];
    __shared__ float s_ms[16];
    __shared__ float s_mc[16];
    __shared__ float s_md;
    __shared__ float s_mean;
    int tid  = threadIdx.x;
    int warp = tid >> 5;
    int lane = tid & 31;
    const float4 z4 = make_float4(0.f, 0.f, 0.f, 0.f);

    if (tid < DD) s_v[tid] = 0.0f;
    if (warp == 0) {   // maxden from per-cloud maxes
        float m = fmaxf(g_blkmax[lane], g_blkmax[lane + 32]);
        #pragma unroll
        for (int o = 16; o > 0; o >>= 1)
            m = fmaxf(m, __shfl_xor_sync(0xffffffffu, m, o));
        if (lane == 0) s_md = fmaxf(m, 1.0f);
    }

    const int base = blockIdx.x * (16 * RPW) + warp * RPW;

    // batch ALL row loads first (max MLP)
    float4 x0[RPW], x1[RPW], x2[RPW];
    #pragma unroll
    for (int i = 0; i < RPW; ++i) {
        const float4* rp = (const float4*)(cm + (size_t)(base + i) * DD);
        x0[i] = rp[lane];
        x1[i] = rp[32 + lane];
        x2[i] = (lane < 16) ? rp[64 + lane] : z4;
    }
    __syncthreads();
    float maxden = s_md;

    float bfac[RPW];
    int   cls[RPW];
    float4 a0 = z4, a1 = z4, a2 = z4;
    #pragma unroll
    for (int i = 0; i < RPW; ++i) {
        int s = base + i;
        float ss = x0[i].x * x0[i].x + x0[i].y * x0[i].y + x0[i].z * x0[i].z + x0[i].w * x0[i].w
                 + x1[i].x * x1[i].x + x1[i].y * x1[i].y + x1[i].z * x1[i].z + x1[i].w * x1[i].w
                 + x2[i].x * x2[i].x + x2[i].y * x2[i].y + x2[i].z * x2[i].z + x2[i].w * x2[i].w;
        #pragma unroll
        for (int o = 16; o > 0; o >>= 1) ss += __shfl_xor_sync(0xffffffffu, ss, o);
        float invn = 1.0f / fmaxf(sqrtf(ss), EPSN);
        cls[i]  = g_cls[s];
        bfac[i] = cls[i] ? invn : 0.0f;
        float a = cls[i] ? invn * (g_counts[s] / maxden) : 0.0f;
        a0.x += x0[i].x * a; a0.y += x0[i].y * a; a0.z += x0[i].z * a; a0.w += x0[i].w * a;
        a1.x += x1[i].x * a; a1.y += x1[i].y * a; a1.z += x1[i].z * a; a1.w += x1[i].w * a;
        a2.x += x2[i].x * a; a2.y += x2[i].y * a; a2.z += x2[i].z * a; a2.w += x2[i].w * a;
    }
    // block v-partial: smem atomics (16 warps, distinct addrs per lane)
    atomicAdd(&s_v[4 * lane + 0], a0.x); atomicAdd(&s_v[4 * lane + 1], a0.y);
    atomicAdd(&s_v[4 * lane + 2], a0.z); atomicAdd(&s_v[4 * lane + 3], a0.w);
    atomicAdd(&s_v[128 + 4 * lane + 0], a1.x); atomicAdd(&s_v[128 + 4 * lane + 1], a1.y);
    atomicAdd(&s_v[128 + 4 * lane + 2], a1.z); atomicAdd(&s_v[128 + 4 * lane + 3], a1.w);
    if (lane < 16) {
        atomicAdd(&s_v[256 + 4 * lane + 0], a2.x); atomicAdd(&s_v[256 + 4 * lane + 1], a2.y);
        atomicAdd(&s_v[256 + 4 * lane + 2], a2.z); atomicAdd(&s_v[256 + 4 * lane + 3], a2.w);
    }
    __syncthreads();
    if (tid < DD) g_vpart[blockIdx.x * DD + tid] = s_v[tid];   // plain coalesced STG
    __threadfence();
    __syncthreads();

    // ---- grid sync #1 (monotonic round counter) ----
    if (tid == 0) {
        int arr = atomicAdd(&g_sync1, 1);
        int tgt = (arr / FBLK + 1) * FBLK;
        while (*(volatile int*)&g_sync1 < tgt) __nanosleep(64);
        __threadfence();
    }
    __syncthreads();

    // column-sum the 128 partials (coalesced; ~160KB L2 per block)
    if (tid < DD) {
        float v = 0.0f;
        #pragma unroll 4
        for (int b = 0; b < FBLK; ++b) v += __ldcg(&g_vpart[b * DD + tid]);
        s_v[tid] = v;
    }
    __syncthreads();

    const float4* v4 = (const float4*)s_v;
    float4 v0 = v4[lane];
    float4 v1 = v4[32 + lane];
    float4 v2 = (lane < 16) ? v4[64 + lane] : z4;

    float sim[RPW];
    float psum = 0.0f, pcnt = 0.0f;
    #pragma unroll
    for (int i = 0; i < RPW; ++i) {
        float dot = x0[i].x * v0.x + x0[i].y * v0.y + x0[i].z * v0.z + x0[i].w * v0.w
                  + x1[i].x * v1.x + x1[i].y * v1.y + x1[i].z * v1.z + x1[i].w * v1.w
                  + x2[i].x * v2.x + x2[i].y * v2.y + x2[i].z * v2.z + x2[i].w * v2.w;
        #pragma unroll
        for (int o = 16; o > 0; o >>= 1) dot += __shfl_xor_sync(0xffffffffu, dot, o);
        sim[i] = bfac[i] * dot;
        if (lane == 0) {
            out_sim[base + i] = sim[i];
            if (cls[i]) { psum += sim[i]; pcnt += 1.0f; }
        }
    }
    if (lane == 0) { s_ms[warp] = psum; s_mc[warp] = pcnt; }
    __syncthreads();
    if (tid == 0) {
        float bs = 0.0f, bc = 0.0f;
        #pragma unroll
        for (int w = 0; w < 16; ++w) { bs += s_ms[w]; bc += s_mc[w]; }
        g_msum_p[blockIdx.x] = bs;   // plain stores
        g_mcnt_p[blockIdx.x] = bc;
    }
    __threadfence();
    __syncthreads();

    // ---- grid sync #2 ----
    if (tid == 0) {
        int arr = atomicAdd(&g_sync2, 1);
        int tgt = (arr / FBLK + 1) * FBLK;
        while (*(volatile int*)&g_sync2 < tgt) __nanosleep(64);
        __threadfence();
    }
    __syncthreads();

    if (warp == 0) {   // redundant tiny mean reduce per block
        float bs = 0.0f, bc = 0.0f;
        #pragma unroll
        for (int j = 0; j < 4; ++j) {
            bs += *(volatile float*)&g_msum_p[lane + 32 * j];
            bc += *(volatile float*)&g_mcnt_p[lane + 32 * j];
        }
        #pragma unroll
        for (int o = 16; o > 0; o >>= 1) {
            bs += __shfl_xor_sync(0xffffffffu, bs, o);
            bc += __shfl_xor_sync(0xffffffffu, bc, o);
        }
        if (lane == 0) s_mean = bs / fmaxf(bc, 1.0f);
    }
    __syncthreads();
    float mean = s_mean;
    if (lane == 0) {
        #pragma unroll
        for (int i = 0; i < RPW; ++i)
            out_clean[base + i] = ((sim[i] > mean) && cls[i]) ? 1.0f : 0.0f;
    }
}

// ---------------- launch ----------------
extern "C" void kernel_launch(void* const* d_in, const int* in_sizes, int n_in,
                              void* d_out, int out_size) {
    const float* feat  = (const float*)d_in[0];
    const float* label = (const float*)d_in[1];
    const int*   clab  = (const int*)d_in[2];
    float* out = (float*)d_out;
    float* out_cm    = out;
    float* out_sim   = out + (size_t)SS * DD;
    float* out_clean = out + (size_t)SS * DD + SS;

    k_counts<<<KK, 512>>>(label, clab);
    k_gather<<<KK * NB, 512>>>(feat, out_cm);
    k_fused<<<FBLK, FTPB>>>(out_cm, out_sim, out_clean);
}